// round 11
// baseline (speedup 1.0000x reference)
#include <cuda_runtime.h>
#include <mma.h>
#include <cstdint>

using namespace nvcuda;

#define DM 1024
#define NH 16
#define DH 64
#define NB 2
#define NS 2048
#define MTOT (NB*NS)
#define SCALE_LOG2E 0.18033688011112042f   // log2(e)/8

// Scratch: head-split projections [B, H, S, DH] (tf32-rounded; Q pre-scaled)
__device__ float g_Q[NB*NH*NS*DH];
__device__ float g_K[NB*NH*NS*DH];
__device__ float g_V[NB*NH*NS*DH];
// Pre-converted (tf32-rounded) proj inputs
__device__ float g_Xc[3ull*MTOT*DM];
__device__ float g_Wc[3ull*DM*DM];
// Split-K partials
__device__ float g_Op[2ull*NB*NH*16*128*64];
__device__ float g_Lp[2ull*NB*NH*16*128];

__device__ __forceinline__ float cvt_tf32(float x) {
    uint32_t r;
    asm("cvt.rna.tf32.f32 %0, %1;" : "=r"(r) : "f"(x));
    return __uint_as_float(r);
}
__device__ __forceinline__ float4 tf32x4(float4 v) {
    v.x = cvt_tf32(v.x); v.y = cvt_tf32(v.y); v.z = cvt_tf32(v.z); v.w = cvt_tf32(v.w);
    return v;
}
// exp2 on the FMA/ALU pipes (no MUFU). Valid for |x| < ~120.
__device__ __forceinline__ float exp2poly(float x) {
    const float C = 12582912.0f;            // 2^23 + 2^22
    float t = x + C;                        // round-to-nearest-int in mantissa
    int   i = __float_as_int(t);
    float n = t - C;
    float f = x - n;                        // f in [-0.5, 0.5]
    float p =           0.00961813f;
    p = fmaf(p, f,      0.05550411f);
    p = fmaf(p, f,      0.24022651f);
    p = fmaf(p, f,      0.69314718f);
    p = fmaf(p, f,      1.00000000f);
    return p * __int_as_float((i + 127) << 23);   // * 2^n
}
__device__ __forceinline__ uint32_t smem_u32(const void* p) {
    uint32_t a;
    asm("{ .reg .u64 t; cvta.to.shared.u64 t, %1; cvt.u32.u64 %0, t; }" : "=r"(a) : "l"(p));
    return a;
}
__device__ __forceinline__ void cpa16(uint32_t dst, const float* src) {
    asm volatile("cp.async.cg.shared.global [%0], [%1], 16;" :: "r"(dst), "l"(src) : "memory");
}
#define CP_COMMIT() asm volatile("cp.async.commit_group;" ::: "memory")
#define CP_WAIT0()  asm volatile("cp.async.wait_group 0;" ::: "memory")

typedef wmma::fragment<wmma::matrix_a, 16, 16, 8, wmma::precision::tf32, wmma::row_major> FragA;
typedef wmma::fragment<wmma::matrix_b, 16, 16, 8, wmma::precision::tf32, wmma::col_major> FragBc;
typedef wmma::fragment<wmma::matrix_b, 16, 16, 8, wmma::precision::tf32, wmma::row_major> FragBr;
typedef wmma::fragment<wmma::accumulator, 16, 16, 8, float> FragC;

// ---------------------------------------------------------------------------
// Pre-convert: tf32-round inputs so proj can cp.async them raw.
// ---------------------------------------------------------------------------
__global__ __launch_bounds__(256) void cvt_pre(const float* __restrict__ s,
                                               float* __restrict__ d, int n4)
{
    int i = blockIdx.x * 256 + threadIdx.x;
    if (i < n4) ((float4*)d)[i] = tf32x4(((const float4*)s)[i]);
}

// ---------------------------------------------------------------------------
// Projection: C = Xc @ Wc^T (tf32 wmma), tile 128x128, 8 warps (4m x 2n),
// warp 32x64, k staged 32, cp.async double-buffered (inputs pre-rounded).
// ---------------------------------------------------------------------------
#define PJ_STRIDE 36
#define PJ_TILE (128*PJ_STRIDE)
#define PJ_SMEM (4*PJ_TILE*4)
#define CS_LD 132

__global__ __launch_bounds__(256, 2) void proj_tc()
{
    extern __shared__ float sm[];
    float* As = sm;
    float* Bs = sm + 2*PJ_TILE;
    const uint32_t as_u = smem_u32(As);
    const uint32_t bs_u = smem_u32(Bs);

    const float* X = g_Xc + (size_t)blockIdx.z * MTOT * DM;
    const float* W = g_Wc + (size_t)blockIdx.z * DM * DM;
    float* out = (blockIdx.z == 0) ? g_Q : (blockIdx.z == 1) ? g_K : g_V;

    const int tid = threadIdx.x;
    const int wid = tid >> 5;
    const int mw = wid & 3, nw = wid >> 2;
    const int bm = blockIdx.x * 128, bn = blockIdx.y * 128;

    FragC c[2][4];
#pragma unroll
    for (int i = 0; i < 2; i++)
#pragma unroll
        for (int j = 0; j < 4; j++) wmma::fill_fragment(c[i][j], 0.0f);

    // Issue k-stage 0 into buffer 0
    for (int c2 = tid; c2 < 1024; c2 += 256) {
        const int row = c2 >> 3, col = (c2 & 7) << 2;
        cpa16(as_u + (row*PJ_STRIDE + col)*4, X + (size_t)(bm + row)*DM + col);
        cpa16(bs_u + (row*PJ_STRIDE + col)*4, W + (size_t)(bn + row)*DM + col);
    }
    CP_COMMIT();

    const int NSTG = DM / 32;
    for (int s = 0; s < NSTG; s++) {
        CP_WAIT0();
        __syncthreads();
        if (s + 1 < NSTG) {
            const int k0 = (s + 1) * 32;
            const uint32_t ab = as_u + ((s + 1) & 1) * PJ_TILE * 4;
            const uint32_t bb = bs_u + ((s + 1) & 1) * PJ_TILE * 4;
            for (int c2 = tid; c2 < 1024; c2 += 256) {
                const int row = c2 >> 3, col = (c2 & 7) << 2;
                cpa16(ab + (row*PJ_STRIDE + col)*4, X + (size_t)(bm + row)*DM + k0 + col);
                cpa16(bb + (row*PJ_STRIDE + col)*4, W + (size_t)(bn + row)*DM + k0 + col);
            }
            CP_COMMIT();
        }
        const float* Ab = As + (s & 1) * PJ_TILE;
        const float* Bb = Bs + (s & 1) * PJ_TILE;
#pragma unroll
        for (int ks = 0; ks < 4; ks++) {
            FragA a[2];
#pragma unroll
            for (int i = 0; i < 2; i++)
                wmma::load_matrix_sync(a[i], Ab + (32*mw + 16*i)*PJ_STRIDE + ks*8, PJ_STRIDE);
#pragma unroll
            for (int j = 0; j < 4; j++) {
                FragBc bfr;
                wmma::load_matrix_sync(bfr, Bb + (64*nw + 16*j)*PJ_STRIDE + ks*8, PJ_STRIDE);
                wmma::mma_sync(c[0][j], a[0], bfr, c[0][j]);
                wmma::mma_sync(c[1][j], a[1], bfr, c[1][j]);
            }
        }
    }
    __syncthreads();

    float* Cs = sm;
#pragma unroll
    for (int i = 0; i < 2; i++)
#pragma unroll
        for (int j = 0; j < 4; j++)
            wmma::store_matrix_sync(Cs + (32*mw + 16*i)*CS_LD + 64*nw + 16*j,
                                    c[i][j], CS_LD, wmma::mem_row_major);
    __syncthreads();

    {
        const float scl = (blockIdx.z == 0) ? SCALE_LOG2E : 1.0f;
        const int r = tid >> 1;
        const int coff = (tid & 1) * 64;
        const int m = bm + r;
        const int b_ = m >> 11, s_ = m & (NS - 1);
        const int n0 = bn + coff;
        const int h = n0 >> 6;
        float* op = out + ((size_t)(b_*NH + h)*NS + s_)*DH;
#pragma unroll
        for (int q = 0; q < 16; q++) {
            float4 v = *(const float4*)&Cs[r*CS_LD + coff + q*4];
            v.x *= scl; v.y *= scl; v.z *= scl; v.w *= scl;
            *(float4*)(op + q*4) = tf32x4(v);
        }
    }
}

// ---------------------------------------------------------------------------
// Attention, split-K x2 (as round-9), with MUFU-free exp2 polynomial.
// smem: Ks[2][128][68] | Vs[2][128][72] | Ps[8][32][72] | Ls[128]
// ---------------------------------------------------------------------------
#define LD_K 68
#define LD_V 72
#define LD_P 72
#define OFF_V (2*128*LD_K)
#define OFF_P (OFF_V + 2*128*LD_V)
#define OFF_L (OFF_P + 8*32*LD_P)
#define AT_FLOATS (OFF_L + 128)
#define AT_SMEM (AT_FLOATS*4)

__global__ __launch_bounds__(256) void attn_tc()
{
    extern __shared__ float sm[];
    float* Ks = sm;
    float* Vs = sm + OFF_V;
    float* Ps = sm + OFF_P;
    float* Ls = sm + OFF_L;
    const uint32_t ks_u = smem_u32(Ks);
    const uint32_t vs_u = smem_u32(Vs);

    const int tid = threadIdx.x;
    const int wid = tid >> 5, lane = tid & 31;
    const int mw = wid & 3, nw = wid >> 2;
    const int qt = blockIdx.x >> 1, half = blockIdx.x & 1;
    const int h = blockIdx.y, b = blockIdx.z;
    const int kt0 = half * 8, kt1 = kt0 + 8;

    const float* Qg = g_Q + ((size_t)(b*NH + h)*NS + qt*128) * DH;
    const float* Kg = g_K + (size_t)(b*NH + h)*NS * DH;
    const float* Vg = g_V + (size_t)(b*NH + h)*NS * DH;

    // Issue first K/V tile (kt0 even -> buffer 0)
    for (int c2 = tid; c2 < 2048; c2 += 256) {
        const int row = c2 >> 4, col = (c2 & 15) << 2;
        const size_t gofs = (size_t)kt0*128*DH + (size_t)row*DH + col;
        cpa16(ks_u + (row*LD_K + col)*4, Kg + gofs);
        cpa16(vs_u + (row*LD_V + col)*4, Vg + gofs);
    }
    CP_COMMIT();

    float* Pw = Ps + wid*32*LD_P;

    // Layout probe: C[m][n] = m reveals each accumulator element's row
    int rowof[8];
    {
        for (int e = lane; e < 128; e += 32) {
            int m = e >> 3, k = e & 7;
            Pw[m*8 + k] = (k == 0) ? (float)m : 0.0f;
            Pw[128 + m*8 + k] = (k == 0) ? 1.0f : 0.0f;
        }
        __syncwarp();
        FragA pa; wmma::load_matrix_sync(pa, Pw, 8);
        FragBc pb; wmma::load_matrix_sync(pb, Pw + 128, 8);
        FragC pc; wmma::fill_fragment(pc, 0.0f);
        wmma::mma_sync(pc, pa, pb, pc);
#pragma unroll
        for (int e = 0; e < 8; e++) rowof[e] = (int)pc.x[e];
    }
    __syncthreads();

    // Stage Q (scaled+tf32) into Ps region; init Ls
    {
        const int sr = tid >> 4, sc4 = (tid & 15) * 4;
#pragma unroll
        for (int p = 0; p < 8; p++)
            *(float4*)&Ps[(sr + p*16)*LD_K + sc4] =
                *(const float4*)(Qg + (size_t)(sr + p*16)*DH + sc4);
        if (tid < 128) Ls[tid] = 0.0f;
    }
    __syncthreads();
    FragA qa[2][8];
#pragma unroll
    for (int i = 0; i < 2; i++)
#pragma unroll
        for (int ks = 0; ks < 8; ks++)
            wmma::load_matrix_sync(qa[i][ks], Ps + (32*mw + 16*i)*LD_K + ks*8, LD_K);

    FragC o[2][4];
#pragma unroll
    for (int i = 0; i < 2; i++)
#pragma unroll
        for (int j = 0; j < 4; j++) wmma::fill_fragment(o[i][j], 0.0f);
    float lacc[2][8];
#pragma unroll
    for (int i = 0; i < 2; i++)
#pragma unroll
        for (int e = 0; e < 8; e++) lacc[i][e] = 0.0f;

    for (int kt = kt0; kt < kt1; kt++) {
        CP_WAIT0();
        __syncthreads();
        if (kt + 1 < kt1) {
            const size_t key0 = (size_t)(kt + 1) * 128 * DH;
            const uint32_t kb = ks_u + ((kt + 1) & 1) * 128*LD_K*4;
            const uint32_t vb = vs_u + ((kt + 1) & 1) * 128*LD_V*4;
            for (int c2 = tid; c2 < 2048; c2 += 256) {
                const int row = c2 >> 4, col = (c2 & 15) << 2;
                cpa16(kb + (row*LD_K + col)*4, Kg + key0 + (size_t)row*DH + col);
                cpa16(vb + (row*LD_V + col)*4, Vg + key0 + (size_t)row*DH + col);
            }
            CP_COMMIT();
        }
        const float* Kb = Ks + (kt & 1)*128*LD_K;
        const float* Vb = Vs + (kt & 1)*128*LD_V;

#pragma unroll
        for (int jh = 0; jh < 2; jh++) {
            FragC s[2][2];
#pragma unroll
            for (int i = 0; i < 2; i++)
#pragma unroll
                for (int j = 0; j < 2; j++) wmma::fill_fragment(s[i][j], 0.0f);
#pragma unroll
            for (int ks = 0; ks < 8; ks++) {
                FragBc kb2[2];
#pragma unroll
                for (int j = 0; j < 2; j++)
                    wmma::load_matrix_sync(kb2[j],
                        Kb + (64*nw + 32*jh + 16*j)*LD_K + ks*8, LD_K);
#pragma unroll
                for (int j = 0; j < 2; j++) {
                    wmma::mma_sync(s[0][j], qa[0][ks], kb2[j], s[0][j]);
                    wmma::mma_sync(s[1][j], qa[1][ks], kb2[j], s[1][j]);
                }
            }
            // exp on FMA/ALU pipes; accumulate row sums; park P in smem
#pragma unroll
            for (int i = 0; i < 2; i++)
#pragma unroll
                for (int j = 0; j < 2; j++) {
#pragma unroll
                    for (int e = 0; e < 8; e++) {
                        float p = exp2poly(s[i][j].x[e]);
                        s[i][j].x[e] = p;
                        lacc[i][e] += p;
                    }
                    wmma::store_matrix_sync(Pw + (16*i)*LD_P + 32*jh + 16*j,
                                            s[i][j], LD_P, wmma::mem_row_major);
                }
        }
        __syncwarp();

#pragma unroll
        for (int ks = 0; ks < 8; ks++) {
            FragA pa2[2];
#pragma unroll
            for (int i = 0; i < 2; i++)
                wmma::load_matrix_sync(pa2[i], Pw + (16*i)*LD_P + ks*8, LD_P);
#pragma unroll
            for (int j = 0; j < 4; j++) {
                FragBr vbf;
                wmma::load_matrix_sync(vbf, Vb + (64*nw + ks*8)*LD_V + 16*j, LD_V);
                wmma::mma_sync(o[0][j], pa2[0], vbf, o[0][j]);
                wmma::mma_sync(o[1][j], pa2[1], vbf, o[1][j]);
            }
        }
    }

    __syncthreads();
#pragma unroll
    for (int i = 0; i < 2; i++)
#pragma unroll
        for (int e = 0; e < 8; e++)
            atomicAdd(&Ls[32*mw + 16*i + rowof[e]], lacc[i][e]);
    {
        float* Ob = Vs + nw*128*LD_V;
#pragma unroll
        for (int i = 0; i < 2; i++)
#pragma unroll
            for (int j = 0; j < 4; j++)
                wmma::store_matrix_sync(Ob + (32*mw + 16*i)*LD_V + 16*j,
                                        o[i][j], LD_V, wmma::mem_row_major);
    }
    __syncthreads();

    {
        const size_t pbase = (size_t)(b*NH + h)*16 + qt;
        const int rr = tid >> 1, ch = tid & 1;
        const float* O0 = Vs + rr*LD_V;
        const float* O1 = Vs + 128*LD_V + rr*LD_V;
        float* op = g_Op + (size_t)half*NB*NH*16*128*64 + pbase*8192 + rr*64 + ch*32;
        const int c0 = ch * 32;
#pragma unroll
        for (int q = 0; q < 8; q++) {
            float4 v0 = *(const float4*)&O0[c0 + q*4];
            float4 v1 = *(const float4*)&O1[c0 + q*4];
            float4 v = make_float4(v0.x + v1.x, v0.y + v1.y, v0.z + v1.z, v0.w + v1.w);
            *(float4*)(op + q*4) = v;
        }
        if (tid < 128)
            g_Lp[(size_t)half*NB*NH*16*128 + pbase*128 + tid] = Ls[tid];
    }
}

// ---------------------------------------------------------------------------
// Combine: out = (O0 + O1) / (l0 + l1)
// ---------------------------------------------------------------------------
__global__ __launch_bounds__(256) void combine_k(float* __restrict__ out)
{
    const int tid = threadIdx.x;
    const int qt = blockIdx.x, h = blockIdx.y, b = blockIdx.z;
    const size_t pbase = (size_t)(b*NH + h)*16 + qt;
    const size_t HOFS = (size_t)NB*NH*16*128*64;
    const size_t LOFS = (size_t)NB*NH*16*128;
    const int rr = tid >> 1, ch = tid & 1;
    const float l = g_Lp[pbase*128 + rr] + g_Lp[LOFS + pbase*128 + rr];
    const float inv = 1.0f / l;
    const float* P0 = g_Op + pbase*8192 + rr*64 + ch*32;
    const float* P1 = P0 + HOFS;
    float* op = out + ((size_t)b*NS + qt*128 + rr)*DM + h*DH + ch*32;
#pragma unroll
    for (int q = 0; q < 8; q++) {
        float4 v0 = *(const float4*)(P0 + q*4);
        float4 v1 = *(const float4*)(P1 + q*4);
        float4 v = make_float4((v0.x + v1.x)*inv, (v0.y + v1.y)*inv,
                               (v0.z + v1.z)*inv, (v0.w + v1.w)*inv);
        *(float4*)(op + q*4) = v;
    }
}

extern "C" void kernel_launch(void* const* d_in, const int* in_sizes, int n_in,
                              void* d_out, int out_size)
{
    const float* q  = (const float*)d_in[0];
    const float* k  = (const float*)d_in[1];
    const float* v  = (const float*)d_in[2];
    const float* wq = (const float*)d_in[3];
    const float* wk = (const float*)d_in[4];
    const float* wv = (const float*)d_in[5];
    float* out = (float*)d_out;

    float* xc; float* wc;
    cudaGetSymbolAddress((void**)&xc, g_Xc);
    cudaGetSymbolAddress((void**)&wc, g_Wc);

    const int NX4 = MTOT*DM/4, NW4 = DM*DM/4;
    cvt_pre<<<(NX4+255)/256, 256>>>(q,  xc,            NX4);
    cvt_pre<<<(NX4+255)/256, 256>>>(k,  xc + MTOT*DM,  NX4);
    cvt_pre<<<(NX4+255)/256, 256>>>(v,  xc + 2ull*MTOT*DM, NX4);
    cvt_pre<<<(NW4+255)/256, 256>>>(wq, wc,            NW4);
    cvt_pre<<<(NW4+255)/256, 256>>>(wk, wc + DM*DM,    NW4);
    cvt_pre<<<(NW4+255)/256, 256>>>(wv, wc + 2ull*DM*DM, NW4);

    cudaFuncSetAttribute(proj_tc, cudaFuncAttributeMaxDynamicSharedMemorySize, PJ_SMEM);
    cudaFuncSetAttribute(attn_tc, cudaFuncAttributeMaxDynamicSharedMemorySize, AT_SMEM);

    dim3 pg(MTOT / 128, DM / 128, 3);
    proj_tc<<<pg, 256, PJ_SMEM>>>();

    dim3 ag(32, NH, NB);   // x = qt*2 + kv-half
    attn_tc<<<ag, 256, AT_SMEM>>>();

    dim3 cg(16, NH, NB);
    combine_k<<<cg, 256>>>(out);
}

// round 13
// speedup vs baseline: 1.8642x; 1.8642x over previous
#include <cuda_runtime.h>
#include <mma.h>
#include <cuda_fp16.h>
#include <cstdint>

using namespace nvcuda;

#define DM 1024
#define NH 16
#define DH 64
#define NB 2
#define NS 2048
#define MTOT (NB*NS)
#define SCALE_LOG2E 0.18033688011112042f   // log2(e)/8

// Scratch: head-split projections [B, H, S, DH], fp16 (Q pre-scaled)
__device__ __half g_Q[NB*NH*NS*DH];
__device__ __half g_K[NB*NH*NS*DH];
__device__ __half g_V[NB*NH*NS*DH];
// Pre-converted fp16 proj inputs
__device__ __half g_Xc[3ull*MTOT*DM];
__device__ __half g_Wc[3ull*DM*DM];
// Split-K partials (fp32)
__device__ float g_Op[2ull*NB*NH*16*128*64];
__device__ float g_Lp[2ull*NB*NH*16*128];

// exp2 on the FMA/ALU pipes. Valid for |x| < ~120.
__device__ __forceinline__ float exp2poly(float x) {
    const float C = 12582912.0f;            // 2^23 + 2^22
    float t = x + C;
    int   i = __float_as_int(t);
    float n = t - C;
    float f = x - n;                        // [-0.5, 0.5]
    float p =           0.00961813f;
    p = fmaf(p, f,      0.05550411f);
    p = fmaf(p, f,      0.24022651f);
    p = fmaf(p, f,      0.69314718f);
    p = fmaf(p, f,      1.00000000f);
    return p * __int_as_float((i + 127) << 23);
}
__device__ __forceinline__ uint32_t smem_u32(const void* p) {
    uint32_t a;
    asm("{ .reg .u64 t; cvta.to.shared.u64 t, %1; cvt.u32.u64 %0, t; }" : "=r"(a) : "l"(p));
    return a;
}
__device__ __forceinline__ void cpa16(uint32_t dst, const void* src) {
    asm volatile("cp.async.cg.shared.global [%0], [%1], 16;" :: "r"(dst), "l"(src) : "memory");
}
#define CP_COMMIT() asm volatile("cp.async.commit_group;" ::: "memory")
#define CP_WAIT0()  asm volatile("cp.async.wait_group 0;" ::: "memory")

typedef wmma::fragment<wmma::matrix_a, 16, 16, 16, __half, wmma::row_major> FragAh;
typedef wmma::fragment<wmma::matrix_b, 16, 16, 16, __half, wmma::col_major> FragBch;
typedef wmma::fragment<wmma::matrix_b, 16, 16, 16, __half, wmma::row_major> FragBrh;
typedef wmma::fragment<wmma::accumulator, 16, 16, 16, float> FragCh;

// ---------------------------------------------------------------------------
// Pre-convert fp32 -> fp16
// ---------------------------------------------------------------------------
__global__ __launch_bounds__(256) void cvt_pre(const float* __restrict__ s,
                                               __half* __restrict__ d, int n4)
{
    int i = blockIdx.x * 256 + threadIdx.x;
    if (i < n4) {
        float4 v = ((const float4*)s)[i];
        __half2 h0 = __float22half2_rn(make_float2(v.x, v.y));
        __half2 h1 = __float22half2_rn(make_float2(v.z, v.w));
        uint2 u;
        u.x = *(uint32_t*)&h0; u.y = *(uint32_t*)&h1;
        ((uint2*)d)[i] = u;
    }
}

// ---------------------------------------------------------------------------
// Projection: C = Xc @ Wc^T (fp16 wmma, fp32 accum). Tile 128x128, 8 warps
// (4m x 2n), warp 32x64. k staged 64 wide, cp.async double-buffered.
// smem (halves): A[2][128][72] | B[2][128][72]; epilogue Cs fp32 overlays.
// ---------------------------------------------------------------------------
#define LD_PJ 72
#define PJ_HTILE (128*LD_PJ)          // halves per buffer
#define PJ_SMEM (4*PJ_HTILE*2)        // 73728 B
#define CS_LD 132

__global__ __launch_bounds__(256, 2) void proj_tc()
{
    extern __shared__ __half smh[];
    __half* As = smh;
    __half* Bs = smh + 2*PJ_HTILE;
    const uint32_t as_u = smem_u32(As);
    const uint32_t bs_u = smem_u32(Bs);

    const __half* X = g_Xc + (size_t)blockIdx.z * MTOT * DM;
    const __half* W = g_Wc + (size_t)blockIdx.z * DM * DM;
    __half* out = (blockIdx.z == 0) ? g_Q : (blockIdx.z == 1) ? g_K : g_V;

    const int tid = threadIdx.x;
    const int wid = tid >> 5;
    const int mw = wid & 3, nw = wid >> 2;
    const int bm = blockIdx.x * 128, bn = blockIdx.y * 128;

    FragCh c[2][4];
#pragma unroll
    for (int i = 0; i < 2; i++)
#pragma unroll
        for (int j = 0; j < 4; j++) wmma::fill_fragment(c[i][j], 0.0f);

    // Stage 0: 128 rows x 64 halves per operand = 1024 16B chunks each
    for (int c2 = tid; c2 < 1024; c2 += 256) {
        const int row = c2 >> 3, col = (c2 & 7) << 3;
        cpa16(as_u + (row*LD_PJ + col)*2, X + (size_t)(bm + row)*DM + col);
        cpa16(bs_u + (row*LD_PJ + col)*2, W + (size_t)(bn + row)*DM + col);
    }
    CP_COMMIT();

    const int NSTG = DM / 64;
    for (int s = 0; s < NSTG; s++) {
        CP_WAIT0();
        __syncthreads();
        if (s + 1 < NSTG) {
            const int k0 = (s + 1) * 64;
            const uint32_t ab = as_u + ((s + 1) & 1) * PJ_HTILE * 2;
            const uint32_t bb = bs_u + ((s + 1) & 1) * PJ_HTILE * 2;
            for (int c2 = tid; c2 < 1024; c2 += 256) {
                const int row = c2 >> 3, col = (c2 & 7) << 3;
                cpa16(ab + (row*LD_PJ + col)*2, X + (size_t)(bm + row)*DM + k0 + col);
                cpa16(bb + (row*LD_PJ + col)*2, W + (size_t)(bn + row)*DM + k0 + col);
            }
            CP_COMMIT();
        }
        const __half* Ab = As + (s & 1) * PJ_HTILE;
        const __half* Bb = Bs + (s & 1) * PJ_HTILE;
#pragma unroll
        for (int ks = 0; ks < 4; ks++) {
            FragAh a[2];
#pragma unroll
            for (int i = 0; i < 2; i++)
                wmma::load_matrix_sync(a[i], Ab + (32*mw + 16*i)*LD_PJ + ks*16, LD_PJ);
#pragma unroll
            for (int j = 0; j < 4; j++) {
                FragBch bfr;
                wmma::load_matrix_sync(bfr, Bb + (64*nw + 16*j)*LD_PJ + ks*16, LD_PJ);
                wmma::mma_sync(c[0][j], a[0], bfr, c[0][j]);
                wmma::mma_sync(c[1][j], a[1], bfr, c[1][j]);
            }
        }
    }
    __syncthreads();

    // Epilogue: stage C (fp32) into smem, then scatter fp16 head-split
    float* Cs = (float*)smh;
#pragma unroll
    for (int i = 0; i < 2; i++)
#pragma unroll
        for (int j = 0; j < 4; j++)
            wmma::store_matrix_sync(Cs + (32*mw + 16*i)*CS_LD + 64*nw + 16*j,
                                    c[i][j], CS_LD, wmma::mem_row_major);
    __syncthreads();

    {
        const float scl = (blockIdx.z == 0) ? SCALE_LOG2E : 1.0f;
        const int r = tid >> 1;
        const int coff = (tid & 1) * 64;
        const int m = bm + r;
        const int b_ = m >> 11, s_ = m & (NS - 1);
        const int n0 = bn + coff;
        const int h = n0 >> 6;
        __half* op = out + ((size_t)(b_*NH + h)*NS + s_)*DH;
#pragma unroll
        for (int q = 0; q < 8; q++) {
            float4 v0 = *(const float4*)&Cs[r*CS_LD + coff + q*8];
            float4 v1 = *(const float4*)&Cs[r*CS_LD + coff + q*8 + 4];
            __half2 h0 = __float22half2_rn(make_float2(v0.x*scl, v0.y*scl));
            __half2 h1 = __float22half2_rn(make_float2(v0.z*scl, v0.w*scl));
            __half2 h2 = __float22half2_rn(make_float2(v1.x*scl, v1.y*scl));
            __half2 h3 = __float22half2_rn(make_float2(v1.z*scl, v1.w*scl));
            uint4 u;
            u.x = *(uint32_t*)&h0; u.y = *(uint32_t*)&h1;
            u.z = *(uint32_t*)&h2; u.w = *(uint32_t*)&h3;
            *(uint4*)(op + q*8) = u;
        }
    }
}

// ---------------------------------------------------------------------------
// Attention, split-K x2, fp16 operands / fp32 accum.
// CTA = (qt, kv-half, h, b); 8 of 16 key tiles; 8 warps (4m x 2n).
// Layout probe gives (row, col) of each accumulator element -> direct fp16
// P scatter into warp-private smem. lsum via probed rows + atomics.
// smem (halves): K[2][128][72] | V[2][128][72] | P[8][32][72] | Ls(f32 128)
//                | Os(f32 2*128*68)
// ---------------------------------------------------------------------------
#define LD_KH 72
#define HTILE (128*LD_KH)                 // 9216 halves per buffer
#define OFF_VH (2*HTILE)                  // 18432
#define OFF_PH (OFF_VH + 2*HTILE)         // 36864
#define OFF_LS (OFF_PH + 8*32*LD_KH)      // 55296 (halves)
#define OFF_OS (OFF_LS + 256)             // 55552 (halves)
#define LD_O 68
#define AT_SMEM ((OFF_OS + 2*128*LD_O*2)*2)   // 180736 B

__global__ __launch_bounds__(256) void attn_tc()
{
    extern __shared__ __half smh[];
    __half* Ks = smh;
    __half* Vs = smh + OFF_VH;
    __half* Ps = smh + OFF_PH;
    float* Ls = (float*)(smh + OFF_LS);
    float* Os = (float*)(smh + OFF_OS);
    const uint32_t ks_u = smem_u32(Ks);
    const uint32_t vs_u = smem_u32(Vs);

    const int tid = threadIdx.x;
    const int wid = tid >> 5, lane = tid & 31;
    const int mw = wid & 3, nw = wid >> 2;
    const int qt = blockIdx.x >> 1, half_ = blockIdx.x & 1;
    const int h = blockIdx.y, b = blockIdx.z;
    const int kt0 = half_ * 8, kt1 = kt0 + 8;

    const __half* Qg = g_Q + ((size_t)(b*NH + h)*NS + qt*128) * DH;
    const __half* Kg = g_K + (size_t)(b*NH + h)*NS * DH;
    const __half* Vg = g_V + (size_t)(b*NH + h)*NS * DH;

    // Issue first K/V tile (kt0 even -> buffer 0). 1024 16B chunks each.
    for (int c2 = tid; c2 < 1024; c2 += 256) {
        const int row = c2 >> 3, col = (c2 & 7) << 3;
        const size_t gofs = (size_t)kt0*128*DH + (size_t)row*DH + col;
        cpa16(ks_u + (row*LD_KH + col)*2, Kg + gofs);
        cpa16(vs_u + (row*LD_KH + col)*2, Vg + gofs);
    }
    CP_COMMIT();

    __half* Pw = Ps + wid*32*LD_KH;

    // Layout probe: C[m][n] = 16m + n (exact in fp16/fp32)
    int rowof[8], colof[8];
    {
        __half* Aq = Pw;          // 16x16 A, row-major, ldm 16
        __half* Bq = Pw + 256;    // 16x16 B, col-major, ldm 16
        for (int e = lane; e < 256; e += 32) {
            const int k2 = e & 15, mn = e >> 4;
            Aq[e] = __float2half((k2 == 0) ? (float)mn : (k2 == 1) ? 1.0f : 0.0f);
            Bq[e] = __float2half((k2 == 0) ? 16.0f : (k2 == 1) ? (float)mn : 0.0f);
        }
        __syncwarp();
        FragAh pa; wmma::load_matrix_sync(pa, Aq, 16);
        FragBch pb; wmma::load_matrix_sync(pb, Bq, 16);
        FragCh pc; wmma::fill_fragment(pc, 0.0f);
        wmma::mma_sync(pc, pa, pb, pc);
#pragma unroll
        for (int e = 0; e < 8; e++) {
            const int v = (int)pc.x[e];
            rowof[e] = v >> 4; colof[e] = v & 15;
        }
    }
    __syncthreads();

    // Stage Q (scaled fp16) into Ps region; init Ls
    for (int c2 = tid; c2 < 1024; c2 += 256) {
        const int row = c2 >> 3, col = (c2 & 7) << 3;
        *(uint4*)(smh + OFF_PH + row*LD_KH + col) =
            *(const uint4*)(Qg + (size_t)row*DH + col);
    }
    if (tid < 128) Ls[tid] = 0.0f;
    __syncthreads();
    FragAh qa[2][4];
#pragma unroll
    for (int i = 0; i < 2; i++)
#pragma unroll
        for (int ks = 0; ks < 4; ks++)
            wmma::load_matrix_sync(qa[i][ks],
                smh + OFF_PH + (32*mw + 16*i)*LD_KH + ks*16, LD_KH);
    // Ps reused for P; barrier at top of first tile protects these reads.

    FragCh o[2][4];
#pragma unroll
    for (int i = 0; i < 2; i++)
#pragma unroll
        for (int j = 0; j < 4; j++) wmma::fill_fragment(o[i][j], 0.0f);
    float lacc[2][8];
#pragma unroll
    for (int i = 0; i < 2; i++)
#pragma unroll
        for (int e = 0; e < 8; e++) lacc[i][e] = 0.0f;

    for (int kt = kt0; kt < kt1; kt++) {
        CP_WAIT0();
        __syncthreads();
        if (kt + 1 < kt1) {
            const size_t key0 = (size_t)(kt + 1) * 128 * DH;
            const uint32_t kb = ks_u + ((kt + 1) & 1) * HTILE * 2;
            const uint32_t vb = vs_u + ((kt + 1) & 1) * HTILE * 2;
            for (int c2 = tid; c2 < 1024; c2 += 256) {
                const int row = c2 >> 3, col = (c2 & 7) << 3;
                cpa16(kb + (row*LD_KH + col)*2, Kg + key0 + (size_t)row*DH + col);
                cpa16(vb + (row*LD_KH + col)*2, Vg + key0 + (size_t)row*DH + col);
            }
            CP_COMMIT();
        }
        const __half* Kb = Ks + (kt & 1)*HTILE;
        const __half* Vb = Vs + (kt & 1)*HTILE;

        // S = Q @ K^T on warp's 64-key half, two 32-col groups
#pragma unroll
        for (int jh = 0; jh < 2; jh++) {
            FragCh s[2][2];
#pragma unroll
            for (int i = 0; i < 2; i++)
#pragma unroll
                for (int j = 0; j < 2; j++) wmma::fill_fragment(s[i][j], 0.0f);
#pragma unroll
            for (int ks = 0; ks < 4; ks++) {
                FragBch kb2[2];
#pragma unroll
                for (int j = 0; j < 2; j++)
                    wmma::load_matrix_sync(kb2[j],
                        Kb + (64*nw + 32*jh + 16*j)*LD_KH + ks*16, LD_KH);
#pragma unroll
                for (int j = 0; j < 2; j++) {
                    wmma::mma_sync(s[0][j], qa[0][ks], kb2[j], s[0][j]);
                    wmma::mma_sync(s[1][j], qa[1][ks], kb2[j], s[1][j]);
                }
            }
            // exp (FMA pipes); accumulate row sums; scatter fp16 P via probe
#pragma unroll
            for (int i = 0; i < 2; i++)
#pragma unroll
                for (int j = 0; j < 2; j++) {
#pragma unroll
                    for (int e = 0; e < 8; e++) {
                        float p = exp2poly(s[i][j].x[e]);
                        lacc[i][e] += p;
                        Pw[(16*i + rowof[e])*LD_KH + 32*jh + 16*j + colof[e]] =
                            __float2half(p);
                    }
                }
        }
        __syncwarp();

        // O += P @ V over this warp's 64-key slice
#pragma unroll
        for (int ks = 0; ks < 4; ks++) {
            FragAh pa2[2];
#pragma unroll
            for (int i = 0; i < 2; i++)
                wmma::load_matrix_sync(pa2[i], Pw + (16*i)*LD_KH + ks*16, LD_KH);
#pragma unroll
            for (int j = 0; j < 4; j++) {
                FragBrh vbf;
                wmma::load_matrix_sync(vbf, Vb + (64*nw + ks*16)*LD_KH + 16*j, LD_KH);
                wmma::mma_sync(o[0][j], pa2[0], vbf, o[0][j]);
                wmma::mma_sync(o[1][j], pa2[1], vbf, o[1][j]);
            }
        }
    }

    __syncthreads();
    // lsum: probed-row atomics into Ls
#pragma unroll
    for (int i = 0; i < 2; i++)
#pragma unroll
        for (int e = 0; e < 8; e++)
            atomicAdd(&Ls[32*mw + 16*i + rowof[e]], lacc[i][e]);
    // O partials to fp32 staging (nw halves separated)
    {
        float* Ob = Os + nw*128*LD_O;
#pragma unroll
        for (int i = 0; i < 2; i++)
#pragma unroll
            for (int j = 0; j < 4; j++)
                wmma::store_matrix_sync(Ob + (32*mw + 16*i)*LD_O + 16*j,
                                        o[i][j], LD_O, wmma::mem_row_major);
    }
    __syncthreads();

    // Write partial O (nw-halves summed) and partial lsum to gmem
    {
        const size_t pbase = (size_t)(b*NH + h)*16 + qt;
        const int rr = tid >> 1, ch = tid & 1;
        const float* O0 = Os + rr*LD_O;
        const float* O1 = Os + 128*LD_O + rr*LD_O;
        float* op = g_Op + (size_t)half_*NB*NH*16*128*64 + pbase*8192 + rr*64 + ch*32;
        const int c0 = ch * 32;
#pragma unroll
        for (int q = 0; q < 8; q++) {
            float4 v0 = *(const float4*)&O0[c0 + q*4];
            float4 v1 = *(const float4*)&O1[c0 + q*4];
            float4 v = make_float4(v0.x + v1.x, v0.y + v1.y, v0.z + v1.z, v0.w + v1.w);
            *(float4*)(op + q*4) = v;
        }
        if (tid < 128)
            g_Lp[(size_t)half_*NB*NH*16*128 + pbase*128 + tid] = Ls[tid];
    }
}

// ---------------------------------------------------------------------------
// Combine: out = (O0 + O1) / (l0 + l1)
// ---------------------------------------------------------------------------
__global__ __launch_bounds__(256) void combine_k(float* __restrict__ out)
{
    const int tid = threadIdx.x;
    const int qt = blockIdx.x, h = blockIdx.y, b = blockIdx.z;
    const size_t pbase = (size_t)(b*NH + h)*16 + qt;
    const size_t HOFS = (size_t)NB*NH*16*128*64;
    const size_t LOFS = (size_t)NB*NH*16*128;
    const int rr = tid >> 1, ch = tid & 1;
    const float l = g_Lp[pbase*128 + rr] + g_Lp[LOFS + pbase*128 + rr];
    const float inv = 1.0f / l;
    const float* P0 = g_Op + pbase*8192 + rr*64 + ch*32;
    const float* P1 = P0 + HOFS;
    float* op = out + ((size_t)b*NS + qt*128 + rr)*DM + h*DH + ch*32;
#pragma unroll
    for (int q = 0; q < 8; q++) {
        float4 v0 = *(const float4*)(P0 + q*4);
        float4 v1 = *(const float4*)(P1 + q*4);
        float4 v = make_float4((v0.x + v1.x)*inv, (v0.y + v1.y)*inv,
                               (v0.z + v1.z)*inv, (v0.w + v1.w)*inv);
        *(float4*)(op + q*4) = v;
    }
}

extern "C" void kernel_launch(void* const* d_in, const int* in_sizes, int n_in,
                              void* d_out, int out_size)
{
    const float* q  = (const float*)d_in[0];
    const float* k  = (const float*)d_in[1];
    const float* v  = (const float*)d_in[2];
    const float* wq = (const float*)d_in[3];
    const float* wk = (const float*)d_in[4];
    const float* wv = (const float*)d_in[5];
    float* out = (float*)d_out;

    __half* xc; __half* wc;
    cudaGetSymbolAddress((void**)&xc, g_Xc);
    cudaGetSymbolAddress((void**)&wc, g_Wc);

    const int NX4 = MTOT*DM/4, NW4 = DM*DM/4;
    cvt_pre<<<(NX4+255)/256, 256>>>(q,  xc,                NX4);
    cvt_pre<<<(NX4+255)/256, 256>>>(k,  xc + (size_t)MTOT*DM,      NX4);
    cvt_pre<<<(NX4+255)/256, 256>>>(v,  xc + 2ull*MTOT*DM, NX4);
    cvt_pre<<<(NW4+255)/256, 256>>>(wq, wc,                NW4);
    cvt_pre<<<(NW4+255)/256, 256>>>(wk, wc + (size_t)DM*DM,        NW4);
    cvt_pre<<<(NW4+255)/256, 256>>>(wv, wc + 2ull*DM*DM,   NW4);

    cudaFuncSetAttribute(proj_tc, cudaFuncAttributeMaxDynamicSharedMemorySize, PJ_SMEM);
    cudaFuncSetAttribute(attn_tc, cudaFuncAttributeMaxDynamicSharedMemorySize, AT_SMEM);

    dim3 pg(MTOT / 128, DM / 128, 3);
    proj_tc<<<pg, 256, PJ_SMEM>>>();

    dim3 ag(32, NH, NB);   // x = qt*2 + kv-half
    attn_tc<<<ag, 256, AT_SMEM>>>();

    dim3 cg(16, NH, NB);
    combine_k<<<cg, 256>>>(out);
}

// round 14
// speedup vs baseline: 3.0999x; 1.6628x over previous
#include <cuda_runtime.h>
#include <mma.h>
#include <cuda_fp16.h>
#include <cstdint>

using namespace nvcuda;

#define DM 1024
#define NH 16
#define DH 64
#define NB 2
#define NS 2048
#define MTOT (NB*NS)
#define SCALE_LOG2E 0.18033688011112042f   // log2(e)/8

// Scratch: head-split projections [B, H, S, DH], fp16 (Q pre-scaled)
__device__ __half g_Q[NB*NH*NS*DH];
__device__ __half g_K[NB*NH*NS*DH];
__device__ __half g_V[NB*NH*NS*DH];
// Pre-converted fp16 weights only (X converts in-kernel)
__device__ __half g_Wc[3ull*DM*DM];
// Split-K partials (fp32)
__device__ float g_Op[2ull*NB*NH*16*128*64];
__device__ float g_Lp[2ull*NB*NH*16*128];

__device__ __forceinline__ float ex2f(float x) {
    float r;
    asm("ex2.approx.f32 %0, %1;" : "=f"(r) : "f"(x));
    return r;
}
__device__ __forceinline__ uint32_t smem_u32(const void* p) {
    uint32_t a;
    asm("{ .reg .u64 t; cvta.to.shared.u64 t, %1; cvt.u32.u64 %0, t; }" : "=r"(a) : "l"(p));
    return a;
}
__device__ __forceinline__ void cpa16(uint32_t dst, const void* src) {
    asm volatile("cp.async.cg.shared.global [%0], [%1], 16;" :: "r"(dst), "l"(src) : "memory");
}
#define CP_COMMIT() asm volatile("cp.async.commit_group;" ::: "memory")
#define CP_WAIT0()  asm volatile("cp.async.wait_group 0;" ::: "memory")

__device__ __forceinline__ uint2 f4_to_h4(float4 v) {
    __half2 h0 = __float22half2_rn(make_float2(v.x, v.y));
    __half2 h1 = __float22half2_rn(make_float2(v.z, v.w));
    uint2 u;
    u.x = *(uint32_t*)&h0; u.y = *(uint32_t*)&h1;
    return u;
}

typedef wmma::fragment<wmma::matrix_a, 16, 16, 16, __half, wmma::row_major> FragAh;
typedef wmma::fragment<wmma::matrix_b, 16, 16, 16, __half, wmma::col_major> FragBch;
typedef wmma::fragment<wmma::matrix_b, 16, 16, 16, __half, wmma::row_major> FragBrh;
typedef wmma::fragment<wmma::accumulator, 16, 16, 16, float> FragCh;

// ---------------------------------------------------------------------------
// Pre-convert weights (all three, one launch): fp32 -> fp16
// ---------------------------------------------------------------------------
__global__ __launch_bounds__(256) void cvt_w(const float* __restrict__ wq,
                                             const float* __restrict__ wk,
                                             const float* __restrict__ wv)
{
    const int NW4 = DM*DM/4;
    int i = blockIdx.x * 256 + threadIdx.x;
    const float* s; int off;
    if (i < NW4)            { s = wq; off = i; }
    else if (i < 2*NW4)     { s = wk; off = i - NW4; }
    else if (i < 3*NW4)     { s = wv; off = i - 2*NW4; }
    else return;
    ((uint2*)g_Wc)[i] = f4_to_h4(((const float4*)s)[off]);
}

// ---------------------------------------------------------------------------
// Projection: C = X @ W^T (fp16 wmma, fp32 accum). Tile 128x128, 8 warps
// (4m x 2n), warp 32x64, k staged 64 wide. A: LDG fp32 + in-reg cvt + STS
// (register double-buffered). B: cp.async from pre-converted g_Wc.
// smem (halves): A[2][128][72] | B[2][128][72]; epilogue Cs fp32 overlays.
// ---------------------------------------------------------------------------
#define LD_PJ 72
#define PJ_HTILE (128*LD_PJ)
#define PJ_SMEM (4*PJ_HTILE*2)        // 73728 B
#define CS_LD 132

__global__ __launch_bounds__(256, 2) void proj_tc(
    const float* __restrict__ xq, const float* __restrict__ xk, const float* __restrict__ xv)
{
    extern __shared__ __half smh[];
    __half* As = smh;
    __half* Bs = smh + 2*PJ_HTILE;
    const uint32_t bs_u = smem_u32(Bs);

    const float* X = (blockIdx.z == 0) ? xq : (blockIdx.z == 1) ? xk : xv;
    const __half* W = g_Wc + (size_t)blockIdx.z * DM * DM;
    __half* out = (blockIdx.z == 0) ? g_Q : (blockIdx.z == 1) ? g_K : g_V;

    const int tid = threadIdx.x;
    const int wid = tid >> 5;
    const int mw = wid & 3, nw = wid >> 2;
    const int bm = blockIdx.x * 128, bn = blockIdx.y * 128;

    const int sr = tid >> 4;             // 0..15
    const int sc = (tid & 15) * 4;       // 0..60

    FragCh c[2][4];
#pragma unroll
    for (int i = 0; i < 2; i++)
#pragma unroll
        for (int j = 0; j < 4; j++) wmma::fill_fragment(c[i][j], 0.0f);

    // Prologue: B stage 0 via cp.async; A stage 0 via LDG+cvt+STS
    for (int c2 = tid; c2 < 1024; c2 += 256) {
        const int row = c2 >> 3, col = (c2 & 7) << 3;
        cpa16(bs_u + (row*LD_PJ + col)*2, W + (size_t)(bn + row)*DM + col);
    }
    CP_COMMIT();
    float4 ax[8];
#pragma unroll
    for (int p = 0; p < 8; p++)
        ax[p] = *(const float4*)(X + (size_t)(bm + sr + p*16) * DM + sc);
#pragma unroll
    for (int p = 0; p < 8; p++)
        *(uint2*)&As[(sr + p*16)*LD_PJ + sc] = f4_to_h4(ax[p]);

    const int NSTG = DM / 64;
    for (int s = 0; s < NSTG; s++) {
        CP_WAIT0();
        __syncthreads();                 // A(s) STS + B(s) cp.async visible
        if (s + 1 < NSTG) {
            const int k0 = (s + 1) * 64;
#pragma unroll
            for (int p = 0; p < 8; p++)
                ax[p] = *(const float4*)(X + (size_t)(bm + sr + p*16) * DM + k0 + sc);
            const uint32_t bb = bs_u + ((s + 1) & 1) * PJ_HTILE * 2;
            for (int c2 = tid; c2 < 1024; c2 += 256) {
                const int row = c2 >> 3, col = (c2 & 7) << 3;
                cpa16(bb + (row*LD_PJ + col)*2, W + (size_t)(bn + row)*DM + k0 + col);
            }
            CP_COMMIT();
        }
        const __half* Ab = As + (s & 1) * PJ_HTILE;
        const __half* Bb = Bs + (s & 1) * PJ_HTILE;
#pragma unroll
        for (int ks = 0; ks < 4; ks++) {
            FragAh a[2];
#pragma unroll
            for (int i = 0; i < 2; i++)
                wmma::load_matrix_sync(a[i], Ab + (32*mw + 16*i)*LD_PJ + ks*16, LD_PJ);
#pragma unroll
            for (int j = 0; j < 4; j++) {
                FragBch bfr;
                wmma::load_matrix_sync(bfr, Bb + (64*nw + 16*j)*LD_PJ + ks*16, LD_PJ);
                wmma::mma_sync(c[0][j], a[0], bfr, c[0][j]);
                wmma::mma_sync(c[1][j], a[1], bfr, c[1][j]);
            }
        }
        if (s + 1 < NSTG) {
            __half* Aw = As + ((s + 1) & 1) * PJ_HTILE;
#pragma unroll
            for (int p = 0; p < 8; p++)
                *(uint2*)&Aw[(sr + p*16)*LD_PJ + sc] = f4_to_h4(ax[p]);
        }
    }
    __syncthreads();

    // Epilogue: stage C (fp32) into smem, scatter fp16 head-split
    float* Cs = (float*)smh;
#pragma unroll
    for (int i = 0; i < 2; i++)
#pragma unroll
        for (int j = 0; j < 4; j++)
            wmma::store_matrix_sync(Cs + (32*mw + 16*i)*CS_LD + 64*nw + 16*j,
                                    c[i][j], CS_LD, wmma::mem_row_major);
    __syncthreads();

    {
        const float scl = (blockIdx.z == 0) ? SCALE_LOG2E : 1.0f;
        const int r = tid >> 1;
        const int coff = (tid & 1) * 64;
        const int m = bm + r;
        const int b_ = m >> 11, s_ = m & (NS - 1);
        const int n0 = bn + coff;
        const int h = n0 >> 6;
        __half* op = out + ((size_t)(b_*NH + h)*NS + s_)*DH;
#pragma unroll
        for (int q = 0; q < 8; q++) {
            float4 v0 = *(const float4*)&Cs[r*CS_LD + coff + q*8];
            float4 v1 = *(const float4*)&Cs[r*CS_LD + coff + q*8 + 4];
            v0.x *= scl; v0.y *= scl; v0.z *= scl; v0.w *= scl;
            v1.x *= scl; v1.y *= scl; v1.z *= scl; v1.w *= scl;
            uint2 u0 = f4_to_h4(v0), u1 = f4_to_h4(v1);
            uint4 u = make_uint4(u0.x, u0.y, u1.x, u1.y);
            *(uint4*)(op + q*8) = u;
        }
    }
}

// ---------------------------------------------------------------------------
// Attention, split-K x2, fp16 operands / fp32 accum, MUFU exp, half2 P stores.
// CTA = (qt, kv-half, h, b); 8 of 16 key tiles; 8 warps (4m x 2n).
// smem (halves): K[2][128][72] | V[2][128][72] | P[8][32][72] | Ls(f32 128)
//                | Os(f32 2*128*68)
// ---------------------------------------------------------------------------
#define LD_KH 72
#define HTILE (128*LD_KH)
#define OFF_VH (2*HTILE)
#define OFF_PH (OFF_VH + 2*HTILE)
#define OFF_LS (OFF_PH + 8*32*LD_KH)
#define OFF_OS (OFF_LS + 256)
#define LD_O 68
#define AT_SMEM ((OFF_OS + 2*128*LD_O*2)*2)   // 180736 B

__global__ __launch_bounds__(256) void attn_tc()
{
    extern __shared__ __half smh[];
    __half* Ks = smh;
    __half* Vs = smh + OFF_VH;
    __half* Ps = smh + OFF_PH;
    float* Ls = (float*)(smh + OFF_LS);
    float* Os = (float*)(smh + OFF_OS);
    const uint32_t ks_u = smem_u32(Ks);
    const uint32_t vs_u = smem_u32(Vs);

    const int tid = threadIdx.x;
    const int wid = tid >> 5, lane = tid & 31;
    const int mw = wid & 3, nw = wid >> 2;
    const int qt = blockIdx.x >> 1, half_ = blockIdx.x & 1;
    const int h = blockIdx.y, b = blockIdx.z;
    const int kt0 = half_ * 8, kt1 = kt0 + 8;

    const __half* Qg = g_Q + ((size_t)(b*NH + h)*NS + qt*128) * DH;
    const __half* Kg = g_K + (size_t)(b*NH + h)*NS * DH;
    const __half* Vg = g_V + (size_t)(b*NH + h)*NS * DH;

    // Issue first K/V tile (buffer 0)
    for (int c2 = tid; c2 < 1024; c2 += 256) {
        const int row = c2 >> 3, col = (c2 & 7) << 3;
        const size_t gofs = (size_t)kt0*128*DH + (size_t)row*DH + col;
        cpa16(ks_u + (row*LD_KH + col)*2, Kg + gofs);
        cpa16(vs_u + (row*LD_KH + col)*2, Vg + gofs);
    }
    CP_COMMIT();

    __half* Pw = Ps + wid*32*LD_KH;

    // Layout probe: C[m][n] = 16m + n (exact)
    int rowof[8], colof[8];
    bool paired;
    {
        __half* Aq = Pw;
        __half* Bq = Pw + 256;
        for (int e = lane; e < 256; e += 32) {
            const int k2 = e & 15, mn = e >> 4;
            Aq[e] = __float2half((k2 == 0) ? (float)mn : (k2 == 1) ? 1.0f : 0.0f);
            Bq[e] = __float2half((k2 == 0) ? 16.0f : (k2 == 1) ? (float)mn : 0.0f);
        }
        __syncwarp();
        FragAh pa; wmma::load_matrix_sync(pa, Aq, 16);
        FragBch pb; wmma::load_matrix_sync(pb, Bq, 16);
        FragCh pc; wmma::fill_fragment(pc, 0.0f);
        wmma::mma_sync(pc, pa, pb, pc);
#pragma unroll
        for (int e = 0; e < 8; e++) {
            const int v = (int)pc.x[e];
            rowof[e] = v >> 4; colof[e] = v & 15;
        }
        paired = true;
#pragma unroll
        for (int e = 0; e < 8; e += 2)
            paired = paired && (rowof[e+1] == rowof[e]) &&
                     (colof[e+1] == colof[e] + 1) && ((colof[e] & 1) == 0);
    }
    __syncthreads();

    // Stage Q into Ps region; init Ls
    for (int c2 = tid; c2 < 1024; c2 += 256) {
        const int row = c2 >> 3, col = (c2 & 7) << 3;
        *(uint4*)(smh + OFF_PH + row*LD_KH + col) =
            *(const uint4*)(Qg + (size_t)row*DH + col);
    }
    if (tid < 128) Ls[tid] = 0.0f;
    __syncthreads();
    FragAh qa[2][4];
#pragma unroll
    for (int i = 0; i < 2; i++)
#pragma unroll
        for (int ks = 0; ks < 4; ks++)
            wmma::load_matrix_sync(qa[i][ks],
                smh + OFF_PH + (32*mw + 16*i)*LD_KH + ks*16, LD_KH);

    FragCh o[2][4];
#pragma unroll
    for (int i = 0; i < 2; i++)
#pragma unroll
        for (int j = 0; j < 4; j++) wmma::fill_fragment(o[i][j], 0.0f);
    float lacc[2][8];
#pragma unroll
    for (int i = 0; i < 2; i++)
#pragma unroll
        for (int e = 0; e < 8; e++) lacc[i][e] = 0.0f;

    for (int kt = kt0; kt < kt1; kt++) {
        CP_WAIT0();
        __syncthreads();
        if (kt + 1 < kt1) {
            const size_t key0 = (size_t)(kt + 1) * 128 * DH;
            const uint32_t kb = ks_u + ((kt + 1) & 1) * HTILE * 2;
            const uint32_t vb = vs_u + ((kt + 1) & 1) * HTILE * 2;
            for (int c2 = tid; c2 < 1024; c2 += 256) {
                const int row = c2 >> 3, col = (c2 & 7) << 3;
                cpa16(kb + (row*LD_KH + col)*2, Kg + key0 + (size_t)row*DH + col);
                cpa16(vb + (row*LD_KH + col)*2, Vg + key0 + (size_t)row*DH + col);
            }
            CP_COMMIT();
        }
        const __half* Kb = Ks + (kt & 1)*HTILE;
        const __half* Vb = Vs + (kt & 1)*HTILE;

#pragma unroll
        for (int jh = 0; jh < 2; jh++) {
            FragCh s[2][2];
#pragma unroll
            for (int i = 0; i < 2; i++)
#pragma unroll
                for (int j = 0; j < 2; j++) wmma::fill_fragment(s[i][j], 0.0f);
#pragma unroll
            for (int ks = 0; ks < 4; ks++) {
                FragBch kb2[2];
#pragma unroll
                for (int j = 0; j < 2; j++)
                    wmma::load_matrix_sync(kb2[j],
                        Kb + (64*nw + 32*jh + 16*j)*LD_KH + ks*16, LD_KH);
#pragma unroll
                for (int j = 0; j < 2; j++) {
                    wmma::mma_sync(s[0][j], qa[0][ks], kb2[j], s[0][j]);
                    wmma::mma_sync(s[1][j], qa[1][ks], kb2[j], s[1][j]);
                }
            }
            // exp (MUFU); row sums; paired half2 P scatter
#pragma unroll
            for (int i = 0; i < 2; i++)
#pragma unroll
                for (int j = 0; j < 2; j++) {
                    if (paired) {
#pragma unroll
                        for (int e = 0; e < 8; e += 2) {
                            float p0 = ex2f(s[i][j].x[e]);
                            float p1 = ex2f(s[i][j].x[e+1]);
                            lacc[i][e] += p0; lacc[i][e+1] += p1;
                            __half2 hh = __floats2half2_rn(make_float2(p0, p1).x,
                                                           make_float2(p0, p1).y);
                            *(__half2*)&Pw[(16*i + rowof[e])*LD_KH + 32*jh + 16*j + colof[e]] = hh;
                        }
                    } else {
#pragma unroll
                        for (int e = 0; e < 8; e++) {
                            float p = ex2f(s[i][j].x[e]);
                            lacc[i][e] += p;
                            Pw[(16*i + rowof[e])*LD_KH + 32*jh + 16*j + colof[e]] =
                                __float2half(p);
                        }
                    }
                }
        }
        __syncwarp();

        // O += P @ V over this warp's 64-key slice
#pragma unroll
        for (int ks = 0; ks < 4; ks++) {
            FragAh pa2[2];
#pragma unroll
            for (int i = 0; i < 2; i++)
                wmma::load_matrix_sync(pa2[i], Pw + (16*i)*LD_KH + ks*16, LD_KH);
#pragma unroll
            for (int j = 0; j < 4; j++) {
                FragBrh vbf;
                wmma::load_matrix_sync(vbf, Vb + (64*nw + ks*16)*LD_KH + 16*j, LD_KH);
                wmma::mma_sync(o[0][j], pa2[0], vbf, o[0][j]);
                wmma::mma_sync(o[1][j], pa2[1], vbf, o[1][j]);
            }
        }
    }

    __syncthreads();
#pragma unroll
    for (int i = 0; i < 2; i++)
#pragma unroll
        for (int e = 0; e < 8; e++)
            atomicAdd(&Ls[32*mw + 16*i + rowof[e]], lacc[i][e]);
    {
        float* Ob = Os + nw*128*LD_O;
#pragma unroll
        for (int i = 0; i < 2; i++)
#pragma unroll
            for (int j = 0; j < 4; j++)
                wmma::store_matrix_sync(Ob + (32*mw + 16*i)*LD_O + 16*j,
                                        o[i][j], LD_O, wmma::mem_row_major);
    }
    __syncthreads();

    {
        const size_t pbase = (size_t)(b*NH + h)*16 + qt;
        const int rr = tid >> 1, ch = tid & 1;
        const float* O0 = Os + rr*LD_O;
        const float* O1 = Os + 128*LD_O + rr*LD_O;
        float* op = g_Op + (size_t)half_*NB*NH*16*128*64 + pbase*8192 + rr*64 + ch*32;
        const int c0 = ch * 32;
#pragma unroll
        for (int q = 0; q < 8; q++) {
            float4 v0 = *(const float4*)&O0[c0 + q*4];
            float4 v1 = *(const float4*)&O1[c0 + q*4];
            float4 v = make_float4(v0.x + v1.x, v0.y + v1.y, v0.z + v1.z, v0.w + v1.w);
            *(float4*)(op + q*4) = v;
        }
        if (tid < 128)
            g_Lp[(size_t)half_*NB*NH*16*128 + pbase*128 + tid] = Ls[tid];
    }
}

// ---------------------------------------------------------------------------
// Combine: out = (O0 + O1) / (l0 + l1)
// ---------------------------------------------------------------------------
__global__ __launch_bounds__(256) void combine_k(float* __restrict__ out)
{
    const int tid = threadIdx.x;
    const int qt = blockIdx.x, h = blockIdx.y, b = blockIdx.z;
    const size_t pbase = (size_t)(b*NH + h)*16 + qt;
    const size_t HOFS = (size_t)NB*NH*16*128*64;
    const size_t LOFS = (size_t)NB*NH*16*128;
    const int rr = tid >> 1, ch = tid & 1;
    const float l = g_Lp[pbase*128 + rr] + g_Lp[LOFS + pbase*128 + rr];
    const float inv = 1.0f / l;
    const float* P0 = g_Op + pbase*8192 + rr*64 + ch*32;
    const float* P1 = P0 + HOFS;
    float* op = out + ((size_t)b*NS + qt*128 + rr)*DM + h*DH + ch*32;
#pragma unroll
    for (int q = 0; q < 8; q++) {
        float4 v0 = *(const float4*)(P0 + q*4);
        float4 v1 = *(const float4*)(P1 + q*4);
        float4 v = make_float4((v0.x + v1.x)*inv, (v0.y + v1.y)*inv,
                               (v0.z + v1.z)*inv, (v0.w + v1.w)*inv);
        *(float4*)(op + q*4) = v;
    }
}

extern "C" void kernel_launch(void* const* d_in, const int* in_sizes, int n_in,
                              void* d_out, int out_size)
{
    const float* q  = (const float*)d_in[0];
    const float* k  = (const float*)d_in[1];
    const float* v  = (const float*)d_in[2];
    const float* wq = (const float*)d_in[3];
    const float* wk = (const float*)d_in[4];
    const float* wv = (const float*)d_in[5];
    float* out = (float*)d_out;

    const int NW4 = DM*DM/4;
    cvt_w<<<(3*NW4 + 255)/256, 256>>>(wq, wk, wv);

    cudaFuncSetAttribute(proj_tc, cudaFuncAttributeMaxDynamicSharedMemorySize, PJ_SMEM);
    cudaFuncSetAttribute(attn_tc, cudaFuncAttributeMaxDynamicSharedMemorySize, AT_SMEM);

    dim3 pg(MTOT / 128, DM / 128, 3);
    proj_tc<<<pg, 256, PJ_SMEM>>>(q, k, v);

    dim3 ag(32, NH, NB);   // x = qt*2 + kv-half
    attn_tc<<<ag, 256, AT_SMEM>>>();

    dim3 cg(16, NH, NB);
    combine_k<<<cg, 256>>>(out);
}

// round 15
// speedup vs baseline: 3.1165x; 1.0054x over previous
#include <cuda_runtime.h>
#include <mma.h>
#include <cuda_fp16.h>
#include <cstdint>

using namespace nvcuda;

#define DM 1024
#define NH 16
#define DH 64
#define NB 2
#define NS 2048
#define MTOT (NB*NS)
#define SCALE_LOG2E 0.18033688011112042f   // log2(e)/8

// Scratch: head-split projections [B, H, S, DH], fp16 (Q pre-scaled)
__device__ __half g_Q[NB*NH*NS*DH];
__device__ __half g_K[NB*NH*NS*DH];
__device__ __half g_V[NB*NH*NS*DH];
// Pre-converted fp16 inputs
__device__ __half g_Xc[3ull*MTOT*DM];
__device__ __half g_Wc[3ull*DM*DM];
// Split-K partials (fp32)
__device__ float g_Op[2ull*NB*NH*16*128*64];
__device__ float g_Lp[2ull*NB*NH*16*128];

__device__ __forceinline__ float ex2f(float x) {
    float r;
    asm("ex2.approx.f32 %0, %1;" : "=f"(r) : "f"(x));
    return r;
}
__device__ __forceinline__ uint32_t smem_u32(const void* p) {
    uint32_t a;
    asm("{ .reg .u64 t; cvta.to.shared.u64 t, %1; cvt.u32.u64 %0, t; }" : "=r"(a) : "l"(p));
    return a;
}
__device__ __forceinline__ void cpa16(uint32_t dst, const void* src) {
    asm volatile("cp.async.cg.shared.global [%0], [%1], 16;" :: "r"(dst), "l"(src) : "memory");
}
#define CP_COMMIT() asm volatile("cp.async.commit_group;" ::: "memory")
#define CP_WAIT0()  asm volatile("cp.async.wait_group 0;" ::: "memory")

__device__ __forceinline__ uint2 f4_to_h4(float4 v) {
    __half2 h0 = __float22half2_rn(make_float2(v.x, v.y));
    __half2 h1 = __float22half2_rn(make_float2(v.z, v.w));
    uint2 u;
    u.x = *(uint32_t*)&h0; u.y = *(uint32_t*)&h1;
    return u;
}

typedef wmma::fragment<wmma::matrix_a, 16, 16, 16, __half, wmma::row_major> FragAh;
typedef wmma::fragment<wmma::matrix_b, 16, 16, 16, __half, wmma::col_major> FragBch;
typedef wmma::fragment<wmma::matrix_b, 16, 16, 16, __half, wmma::row_major> FragBrh;
typedef wmma::fragment<wmma::accumulator, 16, 16, 16, float> FragCh;

// ---------------------------------------------------------------------------
// Pre-convert all six inputs fp32 -> fp16 in one launch.
// ---------------------------------------------------------------------------
#define NX4 (MTOT*DM/4)
#define NW4 (DM*DM/4)
__global__ __launch_bounds__(256) void cvt_all(
    const float* __restrict__ q, const float* __restrict__ k, const float* __restrict__ v,
    const float* __restrict__ wq, const float* __restrict__ wk, const float* __restrict__ wv)
{
    const long i = (long)blockIdx.x * 256 + threadIdx.x;
    if (i < 3L*NX4) {
        const int t = (int)(i / NX4), off = (int)(i - (long)t*NX4);
        const float* s = (t == 0) ? q : (t == 1) ? k : v;
        ((uint2*)g_Xc)[i] = f4_to_h4(((const float4*)s)[off]);
    } else {
        const long j = i - 3L*NX4;
        if (j < 3L*NW4) {
            const int t = (int)(j / NW4), off = (int)(j - (long)t*NW4);
            const float* s = (t == 0) ? wq : (t == 1) ? wk : wv;
            ((uint2*)g_Wc)[j] = f4_to_h4(((const float4*)s)[off]);
        }
    }
}

// ---------------------------------------------------------------------------
// Projection: C = X @ W^T (fp16 wmma, fp32 accum). Tile 128x128, 8 warps
// (4m x 2n), warp 32x64, k staged 64 wide, cp.async both operands (fp16).
// smem (halves): A[2][128][72] | B[2][128][72]; epilogue Cs fp32 overlays.
// ---------------------------------------------------------------------------
#define LD_PJ 72
#define PJ_HTILE (128*LD_PJ)
#define PJ_SMEM (4*PJ_HTILE*2)        // 73728 B
#define CS_LD 132

__global__ __launch_bounds__(256, 2) void proj_tc()
{
    extern __shared__ __half smh[];
    __half* As = smh;
    __half* Bs = smh + 2*PJ_HTILE;
    const uint32_t as_u = smem_u32(As);
    const uint32_t bs_u = smem_u32(Bs);

    const __half* X = g_Xc + (size_t)blockIdx.z * MTOT * DM;
    const __half* W = g_Wc + (size_t)blockIdx.z * DM * DM;
    __half* out = (blockIdx.z == 0) ? g_Q : (blockIdx.z == 1) ? g_K : g_V;

    const int tid = threadIdx.x;
    const int wid = tid >> 5;
    const int mw = wid & 3, nw = wid >> 2;
    const int bm = blockIdx.x * 128, bn = blockIdx.y * 128;

    FragCh c[2][4];
#pragma unroll
    for (int i = 0; i < 2; i++)
#pragma unroll
        for (int j = 0; j < 4; j++) wmma::fill_fragment(c[i][j], 0.0f);

    // Stage 0
    for (int c2 = tid; c2 < 1024; c2 += 256) {
        const int row = c2 >> 3, col = (c2 & 7) << 3;
        cpa16(as_u + (row*LD_PJ + col)*2, X + (size_t)(bm + row)*DM + col);
        cpa16(bs_u + (row*LD_PJ + col)*2, W + (size_t)(bn + row)*DM + col);
    }
    CP_COMMIT();

    const int NSTG = DM / 64;
    for (int s = 0; s < NSTG; s++) {
        CP_WAIT0();
        __syncthreads();
        if (s + 1 < NSTG) {
            const int k0 = (s + 1) * 64;
            const uint32_t ab = as_u + ((s + 1) & 1) * PJ_HTILE * 2;
            const uint32_t bb = bs_u + ((s + 1) & 1) * PJ_HTILE * 2;
            for (int c2 = tid; c2 < 1024; c2 += 256) {
                const int row = c2 >> 3, col = (c2 & 7) << 3;
                cpa16(ab + (row*LD_PJ + col)*2, X + (size_t)(bm + row)*DM + k0 + col);
                cpa16(bb + (row*LD_PJ + col)*2, W + (size_t)(bn + row)*DM + k0 + col);
            }
            CP_COMMIT();
        }
        const __half* Ab = As + (s & 1) * PJ_HTILE;
        const __half* Bb = Bs + (s & 1) * PJ_HTILE;
#pragma unroll
        for (int ks = 0; ks < 4; ks++) {
            FragAh a[2];
#pragma unroll
            for (int i = 0; i < 2; i++)
                wmma::load_matrix_sync(a[i], Ab + (32*mw + 16*i)*LD_PJ + ks*16, LD_PJ);
#pragma unroll
            for (int j = 0; j < 4; j++) {
                FragBch bfr;
                wmma::load_matrix_sync(bfr, Bb + (64*nw + 16*j)*LD_PJ + ks*16, LD_PJ);
                wmma::mma_sync(c[0][j], a[0], bfr, c[0][j]);
                wmma::mma_sync(c[1][j], a[1], bfr, c[1][j]);
            }
        }
    }
    __syncthreads();

    // Epilogue: stage C (fp32) into smem, scatter fp16 head-split
    float* Cs = (float*)smh;
#pragma unroll
    for (int i = 0; i < 2; i++)
#pragma unroll
        for (int j = 0; j < 4; j++)
            wmma::store_matrix_sync(Cs + (32*mw + 16*i)*CS_LD + 64*nw + 16*j,
                                    c[i][j], CS_LD, wmma::mem_row_major);
    __syncthreads();

    {
        const float scl = (blockIdx.z == 0) ? SCALE_LOG2E : 1.0f;
        const int r = tid >> 1;
        const int coff = (tid & 1) * 64;
        const int m = bm + r;
        const int b_ = m >> 11, s_ = m & (NS - 1);
        const int n0 = bn + coff;
        const int h = n0 >> 6;
        __half* op = out + ((size_t)(b_*NH + h)*NS + s_)*DH;
#pragma unroll
        for (int q = 0; q < 8; q++) {
            float4 v0 = *(const float4*)&Cs[r*CS_LD + coff + q*8];
            float4 v1 = *(const float4*)&Cs[r*CS_LD + coff + q*8 + 4];
            v0.x *= scl; v0.y *= scl; v0.z *= scl; v0.w *= scl;
            v1.x *= scl; v1.y *= scl; v1.z *= scl; v1.w *= scl;
            uint2 u0 = f4_to_h4(v0), u1 = f4_to_h4(v1);
            uint4 u = make_uint4(u0.x, u0.y, u1.x, u1.y);
            *(uint4*)(op + q*8) = u;
        }
    }
}

// ---------------------------------------------------------------------------
// Attention, split-K x2, fp16/fp32-accum. In-register P (probe-verified
// C->A fragment correspondence, smem fallback). MUFU exp.
// smem (halves): K[2][128][72] | V[2][128][72] | P[8][32][72] | Ls(f32 128)
//                | Os(f32 2*128*68)
// ---------------------------------------------------------------------------
#define LD_KH 72
#define HTILE (128*LD_KH)
#define OFF_VH (2*HTILE)
#define OFF_PH (OFF_VH + 2*HTILE)
#define OFF_LS (OFF_PH + 8*32*LD_KH)
#define OFF_OS (OFF_LS + 256)
#define LD_O 68
#define AT_SMEM ((OFF_OS + 2*128*LD_O*2)*2)   // 180736 B

__global__ __launch_bounds__(256) void attn_tc()
{
    extern __shared__ __half smh[];
    __half* Ks = smh;
    __half* Vs = smh + OFF_VH;
    __half* Ps = smh + OFF_PH;
    float* Ls = (float*)(smh + OFF_LS);
    float* Os = (float*)(smh + OFF_OS);
    const uint32_t ks_u = smem_u32(Ks);
    const uint32_t vs_u = smem_u32(Vs);

    const int tid = threadIdx.x;
    const int wid = tid >> 5, lane = tid & 31;
    const int mw = wid & 3, nw = wid >> 2;
    const int qt = blockIdx.x >> 1, half_ = blockIdx.x & 1;
    const int h = blockIdx.y, b = blockIdx.z;
    const int kt0 = half_ * 8, kt1 = kt0 + 8;

    const __half* Qg = g_Q + ((size_t)(b*NH + h)*NS + qt*128) * DH;
    const __half* Kg = g_K + (size_t)(b*NH + h)*NS * DH;
    const __half* Vg = g_V + (size_t)(b*NH + h)*NS * DH;

    // Issue first K/V tile (buffer 0)
    for (int c2 = tid; c2 < 1024; c2 += 256) {
        const int row = c2 >> 3, col = (c2 & 7) << 3;
        const size_t gofs = (size_t)kt0*128*DH + (size_t)row*DH + col;
        cpa16(ks_u + (row*LD_KH + col)*2, Kg + gofs);
        cpa16(vs_u + (row*LD_KH + col)*2, Vg + gofs);
    }
    CP_COMMIT();

    __half* Pw = Ps + wid*32*LD_KH;

    // --- Probes ---
    int rowof[8], colof[8];
    bool inreg;
    {
        __half* Aq = Pw;
        __half* Bq = Pw + 256;
        // C probe: C[m][n] = 16m + n
        for (int e = lane; e < 256; e += 32) {
            const int k2 = e & 15, mn = e >> 4;
            Aq[e] = __float2half((k2 == 0) ? (float)mn : (k2 == 1) ? 1.0f : 0.0f);
            Bq[e] = __float2half((k2 == 0) ? 16.0f : (k2 == 1) ? (float)mn : 0.0f);
        }
        __syncwarp();
        FragAh pa; wmma::load_matrix_sync(pa, Aq, 16);
        FragBch pb; wmma::load_matrix_sync(pb, Bq, 16);
        FragCh pc; wmma::fill_fragment(pc, 0.0f);
        wmma::mma_sync(pc, pa, pb, pc);
#pragma unroll
        for (int e = 0; e < 8; e++) {
            const int v = (int)pc.x[e];
            rowof[e] = v >> 4; colof[e] = v & 15;
        }
        // A probe: A[m][k] = 16m + k (row-major index = value)
        __syncwarp();
        for (int e = lane; e < 256; e += 32) Aq[e] = __float2half((float)e);
        __syncwarp();
        FragAh pq; wmma::load_matrix_sync(pq, Aq, 16);
        inreg = true;
#pragma unroll
        for (int e = 0; e < (int)FragAh::num_elements; e++) {
            const int v = (int)__half2float(pq.x[e]);
            inreg = inreg && ((v >> 4) == rowof[e & 7]) && ((v & 15) == colof[e & 7]);
        }
    }
    __syncthreads();

    // Stage Q into Ps region; init Ls
    for (int c2 = tid; c2 < 1024; c2 += 256) {
        const int row = c2 >> 3, col = (c2 & 7) << 3;
        *(uint4*)(smh + OFF_PH + row*LD_KH + col) =
            *(const uint4*)(Qg + (size_t)row*DH + col);
    }
    if (tid < 128) Ls[tid] = 0.0f;
    __syncthreads();
    FragAh qa[2][4];
#pragma unroll
    for (int i = 0; i < 2; i++)
#pragma unroll
        for (int ks = 0; ks < 4; ks++)
            wmma::load_matrix_sync(qa[i][ks],
                smh + OFF_PH + (32*mw + 16*i)*LD_KH + ks*16, LD_KH);

    FragCh o[2][4];
#pragma unroll
    for (int i = 0; i < 2; i++)
#pragma unroll
        for (int j = 0; j < 4; j++) wmma::fill_fragment(o[i][j], 0.0f);
    float lacc[2][8];
#pragma unroll
    for (int i = 0; i < 2; i++)
#pragma unroll
        for (int e = 0; e < 8; e++) lacc[i][e] = 0.0f;

    __half pf[2][4][8];   // in-register P: [i][col-tile][C-elem]

    for (int kt = kt0; kt < kt1; kt++) {
        CP_WAIT0();
        __syncthreads();
        if (kt + 1 < kt1) {
            const size_t key0 = (size_t)(kt + 1) * 128 * DH;
            const uint32_t kb = ks_u + ((kt + 1) & 1) * HTILE * 2;
            const uint32_t vb = vs_u + ((kt + 1) & 1) * HTILE * 2;
            for (int c2 = tid; c2 < 1024; c2 += 256) {
                const int row = c2 >> 3, col = (c2 & 7) << 3;
                cpa16(kb + (row*LD_KH + col)*2, Kg + key0 + (size_t)row*DH + col);
                cpa16(vb + (row*LD_KH + col)*2, Vg + key0 + (size_t)row*DH + col);
            }
            CP_COMMIT();
        }
        const __half* Kb = Ks + (kt & 1)*HTILE;
        const __half* Vb = Vs + (kt & 1)*HTILE;

        // S = Q @ K^T on warp's 64-key half, two 32-col groups
#pragma unroll
        for (int jh = 0; jh < 2; jh++) {
            FragCh s[2][2];
#pragma unroll
            for (int i = 0; i < 2; i++)
#pragma unroll
                for (int j = 0; j < 2; j++) wmma::fill_fragment(s[i][j], 0.0f);
#pragma unroll
            for (int ks = 0; ks < 4; ks++) {
                FragBch kb2[2];
#pragma unroll
                for (int j = 0; j < 2; j++)
                    wmma::load_matrix_sync(kb2[j],
                        Kb + (64*nw + 32*jh + 16*j)*LD_KH + ks*16, LD_KH);
#pragma unroll
                for (int j = 0; j < 2; j++) {
                    wmma::mma_sync(s[0][j], qa[0][ks], kb2[j], s[0][j]);
                    wmma::mma_sync(s[1][j], qa[1][ks], kb2[j], s[1][j]);
                }
            }
            // exp (MUFU); row sums; P to regs (or smem fallback)
#pragma unroll
            for (int i = 0; i < 2; i++)
#pragma unroll
                for (int j = 0; j < 2; j++) {
                    if (inreg) {
#pragma unroll
                        for (int e = 0; e < 8; e++) {
                            float p = ex2f(s[i][j].x[e]);
                            lacc[i][e] += p;
                            pf[i][2*jh + j][e] = __float2half(p);
                        }
                    } else {
#pragma unroll
                        for (int e = 0; e < 8; e++) {
                            float p = ex2f(s[i][j].x[e]);
                            lacc[i][e] += p;
                            Pw[(16*i + rowof[e])*LD_KH + 32*jh + 16*j + colof[e]] =
                                __float2half(p);
                        }
                    }
                }
        }
        if (!inreg) __syncwarp();

        // O += P @ V over this warp's 64-key slice
#pragma unroll
        for (int ks = 0; ks < 4; ks++) {
            FragAh pa2[2];
            if (inreg) {
#pragma unroll
                for (int i = 0; i < 2; i++)
#pragma unroll
                    for (int e = 0; e < (int)FragAh::num_elements; e++)
                        pa2[i].x[e] = pf[i][ks][e & 7];
            } else {
#pragma unroll
                for (int i = 0; i < 2; i++)
                    wmma::load_matrix_sync(pa2[i], Pw + (16*i)*LD_KH + ks*16, LD_KH);
            }
#pragma unroll
            for (int j = 0; j < 4; j++) {
                FragBrh vbf;
                wmma::load_matrix_sync(vbf, Vb + (64*nw + ks*16)*LD_KH + 16*j, LD_KH);
                wmma::mma_sync(o[0][j], pa2[0], vbf, o[0][j]);
                wmma::mma_sync(o[1][j], pa2[1], vbf, o[1][j]);
            }
        }
    }

    __syncthreads();
#pragma unroll
    for (int i = 0; i < 2; i++)
#pragma unroll
        for (int e = 0; e < 8; e++)
            atomicAdd(&Ls[32*mw + 16*i + rowof[e]], lacc[i][e]);
    {
        float* Ob = Os + nw*128*LD_O;
#pragma unroll
        for (int i = 0; i < 2; i++)
#pragma unroll
            for (int j = 0; j < 4; j++)
                wmma::store_matrix_sync(Ob + (32*mw + 16*i)*LD_O + 16*j,
                                        o[i][j], LD_O, wmma::mem_row_major);
    }
    __syncthreads();

    {
        const size_t pbase = (size_t)(b*NH + h)*16 + qt;
        const int rr = tid >> 1, ch = tid & 1;
        const float* O0 = Os + rr*LD_O;
        const float* O1 = Os + 128*LD_O + rr*LD_O;
        float* op = g_Op + (size_t)half_*NB*NH*16*128*64 + pbase*8192 + rr*64 + ch*32;
        const int c0 = ch * 32;
#pragma unroll
        for (int q = 0; q < 8; q++) {
            float4 v0 = *(const float4*)&O0[c0 + q*4];
            float4 v1 = *(const float4*)&O1[c0 + q*4];
            float4 v = make_float4(v0.x + v1.x, v0.y + v1.y, v0.z + v1.z, v0.w + v1.w);
            *(float4*)(op + q*4) = v;
        }
        if (tid < 128)
            g_Lp[(size_t)half_*NB*NH*16*128 + pbase*128 + tid] = Ls[tid];
    }
}

// ---------------------------------------------------------------------------
// Combine: out = (O0 + O1) / (l0 + l1). 4x parallel (8 floats/thread).
// ---------------------------------------------------------------------------
__global__ __launch_bounds__(256) void combine_k(float* __restrict__ out)
{
    const int tid = threadIdx.x;
    const int qt = blockIdx.x >> 2, sub = blockIdx.x & 3;
    const int h = blockIdx.y, b = blockIdx.z;
    const size_t pbase = (size_t)(b*NH + h)*16 + qt;
    const size_t HOFS = (size_t)NB*NH*16*128*64;
    const size_t LOFS = (size_t)NB*NH*16*128;
    const int rr = sub*32 + (tid >> 3);
    const int c0 = (tid & 7) * 8;
    const float l = g_Lp[pbase*128 + rr] + g_Lp[LOFS + pbase*128 + rr];
    const float inv = 1.0f / l;
    const float* P0 = g_Op + pbase*8192 + rr*64 + c0;
    const float* P1 = P0 + HOFS;
    float* op = out + ((size_t)b*NS + qt*128 + rr)*DM + h*DH + c0;
#pragma unroll
    for (int q = 0; q < 2; q++) {
        float4 v0 = *(const float4*)(P0 + q*4);
        float4 v1 = *(const float4*)(P1 + q*4);
        float4 v = make_float4((v0.x + v1.x)*inv, (v0.y + v1.y)*inv,
                               (v0.z + v1.z)*inv, (v0.w + v1.w)*inv);
        *(float4*)(op + q*4) = v;
    }
}

extern "C" void kernel_launch(void* const* d_in, const int* in_sizes, int n_in,
                              void* d_out, int out_size)
{
    const float* q  = (const float*)d_in[0];
    const float* k  = (const float*)d_in[1];
    const float* v  = (const float*)d_in[2];
    const float* wq = (const float*)d_in[3];
    const float* wk = (const float*)d_in[4];
    const float* wv = (const float*)d_in[5];
    float* out = (float*)d_out;

    const long NCVT = 3L*NX4 + 3L*NW4;
    cvt_all<<<(unsigned)((NCVT + 255)/256), 256>>>(q, k, v, wq, wk, wv);

    cudaFuncSetAttribute(proj_tc, cudaFuncAttributeMaxDynamicSharedMemorySize, PJ_SMEM);
    cudaFuncSetAttribute(attn_tc, cudaFuncAttributeMaxDynamicSharedMemorySize, AT_SMEM);

    dim3 pg(MTOT / 128, DM / 128, 3);
    proj_tc<<<pg, 256, PJ_SMEM>>>();

    dim3 ag(32, NH, NB);   // x = qt*2 + kv-half
    attn_tc<<<ag, 256, AT_SMEM>>>();

    dim3 cg(64, NH, NB);   // x = qt*4 + row-quarter
    combine_k<<<cg, 256>>>(out);
}